// round 12
// baseline (speedup 1.0000x reference)
#include <cuda_runtime.h>
#include <cuda_bf16.h>
#include <cstdint>

// SIR SDE: 8192 trajectories x 4900 effective steps, sampled every 100 steps (49 samples),
// features: max, (argmax+u)/49, std(diff(log x)).
//
// R12 = R11 (125.7us) + ONE delta: cp.async pipeline deepened 5-buf/4-ahead ->
// 9-buf/8-ahead. Fit from R11: chunk period = max(T_compute, L_eff/AHEAD) with
// L_eff ~ 2us under full load; AHEAD=8 should push the memory term to ~250ns/chunk,
// letting the r0 chain (~300-400ns/chunk) take over as the limiter (~90-105us).
// NBUF=9 > AHEAD=8 preserves the buffer-reuse invariant (a buffer is refilled one
// iteration after its consumer finished). Tail: full drain for the last 8 iterations.

#define BSZ    8192
#define CH     20            // steps per chunk; 100 % CH == 0
#define NCHUNK 245           // 4900 effective steps
#define NBUF   9             // smem buffers per warp
#define AHEAD  8             // chunks in flight
#define WPB    2             // warps per block
#define THREADS (WPB * 32)

__device__ __forceinline__ void cp_async16(uint32_t saddr, const void* gptr) {
    asm volatile("cp.async.ca.shared.global [%0], [%1], 16;" :: "r"(saddr), "l"(gptr));
}
__device__ __forceinline__ void cp_commit() {
    asm volatile("cp.async.commit_group;");
}
template <int N>
__device__ __forceinline__ void cp_wait() {
    asm volatile("cp.async.wait_group %0;" :: "n"(N));
}
__device__ __forceinline__ float sqrt_approx(float x) {
    float r;
    asm("sqrt.approx.f32 %0, %1;" : "=f"(r) : "f"(x));
    return r;
}

__global__ __launch_bounds__(THREADS, 1)
void sir_sde_kernel(const float* __restrict__ cond,
                    const float* __restrict__ dW,
                    const float* __restrict__ u,
                    float* __restrict__ out)
{
    __shared__ float sdw[WPB][NBUF * CH * 32];   // per-warp: 9 bufs x 20 steps x 32 lanes

    const int lane = threadIdx.x & 31;
    const int w    = threadIdx.x >> 5;
    const int b0   = blockIdx.x * THREADS + w * 32;   // first trajectory of this warp
    const int b    = b0 + lane;

    // ---------- per-trajectory parameters ----------
    const float inf_rate = cond[b * 4 + 0];
    const float rec      = cond[b * 4 + 1];
    const float mr       = cond[b * 4 + 2];
    const float vol      = cond[b * 4 + 3];

    const float DT      = 0.01f;
    const float r0_init = __fdiv_rn(inf_rate, rec);
    const float sdt     = sqrtf(DT);
    const float dtmr    = DT * mr;
    const float om      = 1.0f - dtmr;        // r0' = om*r0 + c1 + sqrt(|r0|)*c2
    const float c1      = dtmr * r0_init;
    const float kvol    = vol * sdt;
    const float ndtrec  = -DT * rec;          // q' = q + ndtrec*ni
    const float omr     = 1.0f + ndtrec;      // z' = omr*z + ni   (z = i/DT)

    // ---------- state (s -> q = rec*s, i -> z = i/DT) ----------
    float q  = rec * 0.99f;
    float z  = 1.0f;                          // i0 = 0.01 = DT*1
    float r0 = r0_init;

    // ---------- feature accumulators ----------
    float cur_max = -3.402823466e38f;
    int   cur_arg = 0;
    float prev_lg = 0.0f;
    float sumd = 0.0f, sumd2 = 0.0f;

    // ---------- cp.async chunk copier (per warp, self-contained) ----------
    uint32_t smem_base;
    asm("{ .reg .u64 t; cvta.to.shared.u64 t, %1; cvt.u32.u64 %0, t; }"
        : "=r"(smem_base) : "l"(&sdw[w][0]));

    const char* gbase = (const char*)(dW + b0);

    auto issue_chunk = [&](int c, int bufidx) {
        const char* g = gbase + (size_t)c * CH * BSZ * 4;
        uint32_t sb = smem_base + bufidx * (CH * 128);
#pragma unroll
        for (int i = 0; i < 5; ++i) {
            int f   = i * 512 + lane * 16;      // flat byte offset in this warp's buffer
            int row = f >> 7;                   // /128
            int col = f & 127;
            cp_async16(sb + f, g + (size_t)row * BSZ * 4 + col);
        }
        cp_commit();
    };

    // prologue: chunks 0..AHEAD-1 in flight
#pragma unroll
    for (int p = 0; p < AHEAD; ++p) issue_chunk(p, p);

    const float* sbuf = &sdw[w][0];

#pragma unroll 1
    for (int c = 0; c < NCHUNK; ++c) {
        // Steady state: pending groups here are {c..c+AHEAD-1} -> wait<AHEAD-1> drains
        // chunk c. Tail (no new issues): pending count < AHEAD, so wait<AHEAD-1> would
        // no longer cover chunk c -> full drain for the last AHEAD iterations.
        if (c + AHEAD >= NCHUNK) cp_wait<0>();
        else                     cp_wait<AHEAD - 1>();
        __syncwarp();

        // burst-copy chunk c to registers (conflict-free LDS)
        float dwv[CH];
        const float* sp = sbuf + (c % NBUF) * (CH * 32) + lane;
#pragma unroll
        for (int k = 0; k < CH; ++k) dwv[k] = sp[k * 32];

        // refill chunk c+AHEAD into buffer (c+AHEAD)%NBUF
        // (NBUF > AHEAD: that buffer's consumer was iteration c-(NBUF-AHEAD) -> done)
        if (c + AHEAD < NCHUNK) issue_chunk(c + AHEAD, (c + AHEAD) % NBUF);

        // ---------- 20 Euler-Maruyama steps ----------
#pragma unroll
        for (int k = 0; k < CH; ++k) {
            const float c2 = dwv[k] * kvol;     // off the critical chain
            const float ni = r0 * q;            // newly_infected (= r0*rec*s)
            const float sq = sqrt_approx(fabsf(r0));
            const float t  = fmaf(r0, om, c1);
            r0 = fmaf(sq, c2, t);               // chain: MUFU + FFMA
            q  = fmaf(ni, ndtrec, q);
            z  = fmaf(omr, z, ni);              // i-update in one FFMA (z = i/DT)
        }

        // ---------- sample after steps 99, 199, ..., 4899 ----------
        if (c % 5 == 4) {
            const int j = c / 5;
            float x = DT * z;                   // i = DT*z
            if ((__float_as_uint(x) & 0x7f800000u) == 0x7f800000u) x = 0.0f; // nan/inf -> 0
            x = fmaxf(x, 1e-5f);

            if (x > cur_max) { cur_max = x; cur_arg = j; }
            const float lg = logf(x);
            if (j > 0) {
                const float d = lg - prev_lg;
                sumd  += d;
                sumd2 += d * d;
            }
            prev_lg = lg;
        }
    }

    // ---------- features ----------
    const float max_at = ((float)cur_arg + u[b]) / 49.0f;
    const float mean   = sumd * (1.0f / 48.0f);
    float var = sumd2 * (1.0f / 48.0f) - mean * mean;   // ddof=0
    var = fmaxf(var, 0.0f);

    out[b * 3 + 0] = cur_max;
    out[b * 3 + 1] = max_at;
    out[b * 3 + 2] = sqrtf(var);
}

extern "C" void kernel_launch(void* const* d_in, const int* in_sizes, int n_in,
                              void* d_out, int out_size)
{
    const float* cond = (const float*)d_in[0];   // (8192, 4)
    const float* dW   = (const float*)d_in[1];   // (5000, 8192)
    const float* u    = (const float*)d_in[2];   // (8192,)
    float* out        = (float*)d_out;           // (8192, 3)

    sir_sde_kernel<<<BSZ / THREADS, THREADS>>>(cond, dW, u, out);
}

// round 13
// speedup vs baseline: 1.1306x; 1.1306x over previous
#include <cuda_runtime.h>
#include <cuda_bf16.h>
#include <cstdint>

// SIR SDE: 8192 trajectories x 4900 effective steps, sampled every 100 steps (49 samples),
// features: max, (argmax+u)/49, std(diff(log x)).
//
// R13 = R11 (125.7us best: NBUF=5/AHEAD=4 cp.async pipeline, 128 blocks x 64 thr,
// q = rec*s, z = i/DT) + ONE delta: CH 20 -> 40 (123 chunks instead of 245), amortizing
// the ~140-cyc fixed per-chunk overhead (waits, syncwarp, branches) over 2x the steps.
// Each chunk is consumed as two 20-step half-bursts reusing one dwv[20] array so register
// count stays ~56. Samples fall at k=19 of chunks c%5==2 and k=39 of chunks c%5==4
// (25 + 24 = 49 samples, temporally ordered); a running counter js tracks the sample index.
// Final chunk (c=122) samples after its first half; its second half is harmless overrun
// (dW rows <= 4919 < 5000).

#define BSZ    8192
#define CH     40            // steps per chunk
#define HS     20            // half-chunk steps
#define NCHUNK 123           // covers steps 0..4919 (sample 48 at step 4899)
#define NBUF   5             // smem buffers per warp
#define AHEAD  4             // chunks in flight
#define WPB    2             // warps per block
#define THREADS (WPB * 32)

__device__ __forceinline__ void cp_async16(uint32_t saddr, const void* gptr) {
    asm volatile("cp.async.ca.shared.global [%0], [%1], 16;" :: "r"(saddr), "l"(gptr));
}
__device__ __forceinline__ void cp_commit() {
    asm volatile("cp.async.commit_group;");
}
template <int N>
__device__ __forceinline__ void cp_wait() {
    asm volatile("cp.async.wait_group %0;" :: "n"(N));
}
__device__ __forceinline__ float sqrt_approx(float x) {
    float r;
    asm("sqrt.approx.f32 %0, %1;" : "=f"(r) : "f"(x));
    return r;
}

__global__ __launch_bounds__(THREADS, 1)
void sir_sde_kernel(const float* __restrict__ cond,
                    const float* __restrict__ dW,
                    const float* __restrict__ u,
                    float* __restrict__ out)
{
    __shared__ float sdw[WPB][NBUF * CH * 32];   // per-warp: 5 bufs x 40 steps x 32 lanes

    const int lane = threadIdx.x & 31;
    const int w    = threadIdx.x >> 5;
    const int b0   = blockIdx.x * THREADS + w * 32;   // first trajectory of this warp
    const int b    = b0 + lane;

    // ---------- per-trajectory parameters ----------
    const float inf_rate = cond[b * 4 + 0];
    const float rec      = cond[b * 4 + 1];
    const float mr       = cond[b * 4 + 2];
    const float vol      = cond[b * 4 + 3];

    const float DT      = 0.01f;
    const float r0_init = __fdiv_rn(inf_rate, rec);
    const float sdt     = sqrtf(DT);
    const float dtmr    = DT * mr;
    const float om      = 1.0f - dtmr;        // r0' = om*r0 + c1 + sqrt(|r0|)*c2
    const float c1      = dtmr * r0_init;
    const float kvol    = vol * sdt;
    const float ndtrec  = -DT * rec;          // q' = q + ndtrec*ni
    const float omr     = 1.0f + ndtrec;      // z' = omr*z + ni   (z = i/DT)

    // ---------- state (s -> q = rec*s, i -> z = i/DT) ----------
    float q  = rec * 0.99f;
    float z  = 1.0f;                          // i0 = 0.01 = DT*1
    float r0 = r0_init;

    // ---------- feature accumulators ----------
    float cur_max = -3.402823466e38f;
    int   cur_arg = 0;
    int   js      = 0;                        // running sample index (0..48)
    float prev_lg = 0.0f;
    float sumd = 0.0f, sumd2 = 0.0f;

    // ---------- cp.async chunk copier (per warp, self-contained) ----------
    uint32_t smem_base;
    asm("{ .reg .u64 t; cvta.to.shared.u64 t, %1; cvt.u32.u64 %0, t; }"
        : "=r"(smem_base) : "l"(&sdw[w][0]));

    const char* gbase = (const char*)(dW + b0);

    // chunk = 40 rows x 128 B = 5120 B; thread copies 10 x 16 B.
    auto issue_chunk = [&](int c, int bufidx) {
        const char* g = gbase + (size_t)c * CH * BSZ * 4;
        uint32_t sb = smem_base + bufidx * (CH * 128);
#pragma unroll
        for (int i = 0; i < 10; ++i) {
            int f   = i * 512 + lane * 16;      // flat byte offset in this warp's buffer
            int row = f >> 7;                   // /128
            int col = f & 127;
            cp_async16(sb + f, g + (size_t)row * BSZ * 4 + col);
        }
        cp_commit();
    };

    // 20 Euler-Maruyama steps from a register block
    float dwv[HS];
    auto run_half = [&](void) {
#pragma unroll
        for (int k = 0; k < HS; ++k) {
            const float c2 = dwv[k] * kvol;     // off the critical chain
            const float ni = r0 * q;            // newly_infected (= r0*rec*s)
            const float sq = sqrt_approx(fabsf(r0));
            const float t  = fmaf(r0, om, c1);
            r0 = fmaf(sq, c2, t);               // chain: MUFU + FFMA
            q  = fmaf(ni, ndtrec, q);
            z  = fmaf(omr, z, ni);              // i-update in one FFMA (z = i/DT)
        }
    };

    auto take_sample = [&](void) {
        float x = DT * z;                       // i = DT*z
        if ((__float_as_uint(x) & 0x7f800000u) == 0x7f800000u) x = 0.0f; // nan/inf -> 0
        x = fmaxf(x, 1e-5f);
        if (x > cur_max) { cur_max = x; cur_arg = js; }
        const float lg = logf(x);
        if (js > 0) {
            const float d = lg - prev_lg;
            sumd  += d;
            sumd2 += d * d;
        }
        prev_lg = lg;
        ++js;
    };

    // prologue: chunks 0..AHEAD-1 in flight
#pragma unroll
    for (int p = 0; p < AHEAD; ++p) issue_chunk(p, p);

    const float* sbuf = &sdw[w][0];

#pragma unroll 1
    for (int c = 0; c < NCHUNK; ++c) {
        // Steady state: pending groups {c..c+AHEAD-1} -> wait<AHEAD-1> drains chunk c.
        // Tail (no new issues): pending count < AHEAD -> full drain.
        if (c + AHEAD >= NCHUNK) cp_wait<0>();
        else                     cp_wait<AHEAD - 1>();
        __syncwarp();

        const float* sp = sbuf + (c % NBUF) * (CH * 32) + lane;
        const int cm5 = c % 5;

        // ---- half 0: steps c*40 .. c*40+19 ----
#pragma unroll
        for (int k = 0; k < HS; ++k) dwv[k] = sp[k * 32];

        // refill chunk c+AHEAD into buffer (c+AHEAD)%NBUF
        // (NBUF = AHEAD+1: that buffer's consumer was chunk c-1 -> done)
        if (c + AHEAD < NCHUNK) issue_chunk(c + AHEAD, (c + AHEAD) % NBUF);

        run_half();
        if (cm5 == 2) take_sample();            // global step c*40+19 ≡ 99 (mod 200 pattern)

        // ---- half 1: steps c*40+20 .. c*40+39 ----
#pragma unroll
        for (int k = 0; k < HS; ++k) dwv[k] = sp[(HS + k) * 32];

        run_half();
        if (cm5 == 4) take_sample();            // global step c*40+39
    }

    // ---------- features ----------
    const float max_at = ((float)cur_arg + u[b]) / 49.0f;
    const float mean   = sumd * (1.0f / 48.0f);
    float var = sumd2 * (1.0f / 48.0f) - mean * mean;   // ddof=0
    var = fmaxf(var, 0.0f);

    out[b * 3 + 0] = cur_max;
    out[b * 3 + 1] = max_at;
    out[b * 3 + 2] = sqrtf(var);
}

extern "C" void kernel_launch(void* const* d_in, const int* in_sizes, int n_in,
                              void* d_out, int out_size)
{
    const float* cond = (const float*)d_in[0];   // (8192, 4)
    const float* dW   = (const float*)d_in[1];   // (5000, 8192)
    const float* u    = (const float*)d_in[2];   // (8192,)
    float* out        = (float*)d_out;           // (8192, 3)

    sir_sde_kernel<<<BSZ / THREADS, THREADS>>>(cond, dW, u, out);
}